// round 16
// baseline (speedup 1.0000x reference)
#include <cuda_runtime.h>
#include <cuda_fp16.h>
#include <math.h>
#include <stdint.h>

#define BSZ  16
#define CDIM 384
#define LDIM 4096
#define PDIM 192
#define BLTOK (BSZ*LDIM)      // 65536
#define NCH  64
#define TCH  64
#define KDIM 384

// ---------------- static scratch (no allocations allowed) ----------------
__device__ float g_lam [2*PDIM];     // permuted: slot 2q = re, 2q+1 = im (q = rank)
__device__ float g_lamT[2*PDIM];
__device__ float g_carry[(size_t)BSZ*NCH*CDIM];   // float2 per complex channel
__device__ int   g_rank[PDIM];       // rank q for active p, -1 inactive
__device__ int   g_cnt;              // active pair count
__device__ int   g_nt1;              // active 128-col N tiles for gemm1
__device__ int   g_nch2;             // active 64-wide K chunks for gemm2

// fp16 operands (single fp16 everywhere; quadrature error budget ~5e-4 < 1e-3)
__device__ __half g_buf[(size_t)BLTOK*CDIM];   // Bu fp16, interleaved (re,im), permuted
__device__ __half g_fxh[(size_t)BLTOK*CDIM];
__device__ __half g_buh[(size_t)BLTOK*CDIM];   // xs fp16, interleaved, permuted
__device__ __half g_yh [(size_t)BLTOK*CDIM];   // y fp16
__device__ __half g_fyh[(size_t)BLTOK*CDIM];
__device__ __half g_ggh[(size_t)BLTOK*CDIM];
__device__ __half g_wb[CDIM*CDIM];             // rows 2q/2q+1 (permuted); inactive rows zero
__device__ __half g_wc[CDIM*CDIM];             // cols 2q/2q+1 (permuted); inactive cols zero
__device__ __half g_we[2*CDIM*CDIM];           // interleaved z1/z2 rows
__device__ __half g_wd[CDIM*CDIM];

__device__ __forceinline__ float gelu_f(float v){
    return 0.5f*v*(1.0f + erff(v*0.70710678118654752f));
}
__device__ __forceinline__ uint32_t smem_u32(const void* p){
    uint32_t a;
    asm("{ .reg .u64 t; cvta.to.shared.u64 t, %1; cvt.u32.u64 %0, t; }" : "=r"(a) : "l"(p));
    return a;
}

// ---------------- MMA / ldmatrix / cp.async primitives (sm_80+ neutral PTX) ----------------
#define CP16(sa, ga)  asm volatile("cp.async.cg.shared.global [%0], [%1], 16;" :: "r"(sa), "l"(ga))
#define CPCOMMIT()    asm volatile("cp.async.commit_group;")
#define CPWAIT(n)     asm volatile("cp.async.wait_group %0;" :: "n"(n))

#define LDSM4(r, addr) asm volatile( \
    "ldmatrix.sync.aligned.m8n8.x4.shared.b16 {%0,%1,%2,%3}, [%4];" \
    : "=r"((r)[0]),"=r"((r)[1]),"=r"((r)[2]),"=r"((r)[3]) : "r"(addr))

#define MMA(d, a, b0v, b1v) asm volatile( \
    "mma.sync.aligned.m16n8k16.row.col.f32.f16.f16.f32 " \
    "{%0,%1,%2,%3},{%4,%5,%6,%7},{%8,%9},{%0,%1,%2,%3};" \
    : "+f"((d)[0]),"+f"((d)[1]),"+f"((d)[2]),"+f"((d)[3]) \
    : "r"((a)[0]),"r"((a)[1]),"r"((a)[2]),"r"((a)[3]),"r"(b0v),"r"(b1v))

// ============ fp16 single-pass NT GEMM: C[M,*] = A[M,384] @ B[*,384]^T ============
// NEW: tile 128x128, BK=64, 3-stage cp.async, 16 warps (4x4), warp tile 32x32,
//      512 threads, __launch_bounds__(512,2) -> 32 warps/SM (reg cap 64)
// stage layout: A @0 (128x144B), B @18432 ; stage stride 36864 ; rows padded to 144B
// EPI 1: dynamic K (g_nch2 chunks); f=e0[n]; v=acc+e1[n]*f; outH=fp16(gelu(v)+f)
// EPI 3: GEGLU pairs -> smem staged -> outH fp16 [BL, 384]
// EPI 4: o=acc+e0; write Cout fp32 transposed [B,C,L] via smem staging
// EPI 5: dynamic N (exit tiles >= g_nt1); plain fp16 out -> outH
template<int EPI>
__global__ __launch_bounds__(512,2) void mma_gemm(
    const __half* __restrict__ Ah,
    const __half* __restrict__ Bm,
    float* __restrict__ Cout, int Nout,
    __half* __restrict__ outH,
    const __half* __restrict__ e0h,
    const float* __restrict__ e1)
{
    if (EPI == 5){ if ((int)blockIdx.x >= g_nt1) return; }
    const int nch = (EPI == 1) ? g_nch2 : 6;

    extern __shared__ char smem[];
    uint32_t sb = smem_u32(smem);
    const int tid = threadIdx.x;
    const int bm = blockIdx.y*128, bn = blockIdx.x*128;

    // ---- load indexing: 128 rows x 8 segs of 16B per array; 2 row-groups/thread ----
    const int lr  = tid >> 3;          // row 0..63 (+64*h)
    const int seg = tid & 7;           // 16B segment within 128B row
    const __half* pa0 = Ah + (size_t)(bm+lr)*KDIM + seg*8;
    const __half* pb0 = Bm + (size_t)(bn+lr)*KDIM + seg*8;
    const uint32_t s0 = lr*144 + seg*16;

    // ---- compute indexing: warp grid 4x4, warp tile 32x32 ----
    const int lane = tid & 31, w = tid >> 5;
    const int wm = (w >> 2)*32, wn = (w & 3)*32;
    const uint32_t aoff = (uint32_t)(wm + (lane & 15))*144 + (lane >> 4)*16;
    const int bg = lane >> 3, blg = lane & 7;
    const uint32_t boff = (uint32_t)(wn + (bg >> 1)*8 + blg)*144 + (bg & 1)*16;

    float acc[2][4][4];
    #pragma unroll
    for (int i=0;i<2;i++)
        #pragma unroll
        for (int j=0;j<4;j++)
            #pragma unroll
            for (int q=0;q<4;q++) acc[i][j][q]=0.f;

    auto issue = [&](int st, int kc){
        uint32_t sbase = sb + st*36864;
        #pragma unroll
        for (int h = 0; h < 2; h++){
            size_t rofs = (size_t)kc + (size_t)h*64*KDIM;
            uint32_t sa = sbase + s0 + h*64*144;
            CP16(sa,         pa0 + rofs);
            CP16(sa + 18432, pb0 + rofs);
        }
        CPCOMMIT();
    };

    issue(0, 0);
    issue(1, 64);
    int stg = 0;                        // stage of chunk c
    #pragma unroll 1
    for (int c = 0; c < nch; c++){
        if (c + 1 < nch) { CPWAIT(1); } else { CPWAIT(0); }
        __syncthreads();
        if (c + 2 < nch){
            int st2 = stg + 2; if (st2 >= 3) st2 -= 3;
            issue(st2, (c+2)*64);
        }
        uint32_t base = sb + stg*36864;
        #pragma unroll
        for (int ks = 0; ks < 4; ks++){
            uint32_t kb = ks*32;
            uint32_t a[2][4], bf[4][2], t[4];
            #pragma unroll
            for (int i=0;i<2;i++) LDSM4(a[i], base + aoff + i*16*144 + kb);
            #pragma unroll
            for (int jp=0;jp<2;jp++){
                LDSM4(t, base + 18432 + boff + jp*16*144 + kb);
                bf[2*jp][0]=t[0]; bf[2*jp][1]=t[1]; bf[2*jp+1][0]=t[2]; bf[2*jp+1][1]=t[3];
            }
            #pragma unroll
            for (int i=0;i<2;i++)
                #pragma unroll
                for (int j=0;j<4;j++) MMA(acc[i][j], a[i], bf[j][0], bf[j][1]);
        }
        if (++stg == 3) stg = 0;
    }

    // ---- epilogue ----
    const int r0 = lane >> 2, cc = (lane & 3)*2;
    if (EPI == 1){
        #pragma unroll
        for (int i=0;i<2;i++){
            int row = bm + wm + i*16 + r0;
            #pragma unroll
            for (int j=0;j<4;j++){
                int col = bn + wn + j*8 + cc;
                float v0 = acc[i][j][0], v1 = acc[i][j][1];
                float v2 = acc[i][j][2], v3 = acc[i][j][3];
                float2 d2 = *(const float2*)(e1 + col);
                __half2 h0 = *(const __half2*)(e0h + (size_t)row*CDIM + col);
                __half2 h1 = *(const __half2*)(e0h + (size_t)(row+8)*CDIM + col);
                float f0x = __half2float(h0.x), f0y = __half2float(h0.y);
                float f1x = __half2float(h1.x), f1y = __half2float(h1.y);
                v0 = gelu_f(v0 + d2.x*f0x) + f0x;
                v1 = gelu_f(v1 + d2.y*f0y) + f0y;
                v2 = gelu_f(v2 + d2.x*f1x) + f1x;
                v3 = gelu_f(v3 + d2.y*f1y) + f1y;
                *(__half2*)(outH + (size_t)row*CDIM + col)     = __floats2half2_rn(v0, v1);
                *(__half2*)(outH + (size_t)(row+8)*CDIM + col) = __floats2half2_rn(v2, v3);
            }
        }
    } else if (EPI == 3){
        // GEGLU: even col = z1, odd col = z2 (interleaved W_enc); stage hi in smem
        __half* sth = (__half*)smem;    // [128 rows][72 halves stride]
        __syncthreads();
        #pragma unroll
        for (int i=0;i<2;i++){
            int rl = wm + i*16 + r0;
            #pragma unroll
            for (int j=0;j<4;j++){
                int gcl = (wn >> 1) + j*4 + (lane & 3);
                float g0 = acc[i][j][0] * gelu_f(acc[i][j][1]);
                float g1 = acc[i][j][2] * gelu_f(acc[i][j][3]);
                sth[rl*72 + gcl]     = __float2half_rn(g0);
                sth[(rl+8)*72 + gcl] = __float2half_rn(g1);
            }
        }
        __syncthreads();
        int gcol0 = bn >> 1;
        #pragma unroll
        for (int q = 0; q < 8; q++){
            int rl = w*8 + q;
            uint32_t v = *(const uint32_t*)(sth + rl*72 + 2*lane);
            *(uint32_t*)(outH + (size_t)(bm + rl)*CDIM + gcol0 + 2*lane) = v;
        }
    } else if (EPI == 4){
        // residual add then transposed store to [B, C, L] via smem staging
        float* smf = (float*)smem;      // [128 cols][132 row-stride]
        __syncthreads();
        #pragma unroll
        for (int i=0;i<2;i++){
            int row = bm + wm + i*16 + r0;
            int rl  = wm + i*16 + r0;
            #pragma unroll
            for (int j=0;j<4;j++){
                int col = bn + wn + j*8 + cc;
                int clo = wn + j*8 + cc;
                __half2 h0 = *(const __half2*)(e0h + (size_t)row*CDIM + col);
                __half2 h1 = *(const __half2*)(e0h + (size_t)(row+8)*CDIM + col);
                smf[(clo  )*132 + rl    ] = acc[i][j][0] + __half2float(h0.x);
                smf[(clo+1)*132 + rl    ] = acc[i][j][1] + __half2float(h0.y);
                smf[(clo  )*132 + rl + 8] = acc[i][j][2] + __half2float(h1.x);
                smf[(clo+1)*132 + rl + 8] = acc[i][j][3] + __half2float(h1.y);
            }
        }
        __syncthreads();
        int b  = bm >> 12;
        int l0 = bm & 4095;
        #pragma unroll
        for (int q = 0; q < 8; q++){
            int cl = w*8 + q;
            float4 v = *(const float4*)(smf + cl*132 + lane*4);
            *(float4*)(Cout + ((size_t)b*CDIM + bn + cl)*LDIM + l0 + lane*4) = v;
        }
    } else {
        // EPI 5: plain fp16 store
        #pragma unroll
        for (int i=0;i<2;i++){
            int row = bm + wm + i*16 + r0;
            #pragma unroll
            for (int j=0;j<4;j++){
                int col = bn + wn + j*8 + cc;
                __half2 v01 = __floats2half2_rn(acc[i][j][0], acc[i][j][1]);
                __half2 v23 = __floats2half2_rn(acc[i][j][2], acc[i][j][3]);
                *(__half2*)(outH + (size_t)row*Nout + col)     = v01;
                *(__half2*)(outH + (size_t)(row+8)*Nout + col) = v23;
            }
        }
    }
}

// ---------------- prep: mask + compaction + discretization (single block, 192 thr) ----------------
__global__ void prep_lam(const float* __restrict__ Lam, const float* __restrict__ logstep){
    __shared__ int sm[PDIM];
    int p = threadIdx.x;
    float step = expf(logstep[p]);
    float lre = Lam[2*p], lim = Lam[2*p+1];
    float freq = step*fabsf(lim)*(float)(1.0/(2.0*3.14159265358979323846));
    int act = (freq < 0.25f) ? 1 : 0;
    sm[p] = act;
    __syncthreads();
    for (int off = 1; off < PDIM; off <<= 1){
        int v = (p >= off) ? sm[p-off] : 0;
        __syncthreads();
        sm[p] += v;
        __syncthreads();
    }
    int q = sm[p] - act;
    int cnt = sm[PDIM-1];
    if (act){
        g_rank[p] = q;
        double a  = exp((double)lre*(double)step);
        double th = (double)lim*(double)step;
        g_lam[2*q]   = (float)(a*cos(th));
        g_lam[2*q+1] = (float)(a*sin(th));
        double aT  = exp((double)TCH*(double)lre*(double)step);
        double thT = (double)TCH*th;
        g_lamT[2*q]   = (float)(aT*cos(thT));
        g_lamT[2*q+1] = (float)(aT*sin(thT));
    } else {
        g_rank[p] = -1;
    }
    if (p == 0){
        g_cnt  = cnt;
        g_nch2 = (2*cnt + 63) / 64;
        g_nt1  = (2*cnt + 127) / 128;
    }
}

// one kernel for all weight preps: wb(192) | wc(384) | we(768) | wd(384) blocks
__global__ void prep_all(const float* __restrict__ Lam, const float* __restrict__ logstep,
                         const float* __restrict__ Bmat, const float* __restrict__ Cmat,
                         const float* __restrict__ Wenc, const float* __restrict__ Wdec){
    int bid = blockIdx.x, tid = threadIdx.x;
    if (bid < 192){
        int p = bid, c = tid;
        int q = g_rank[p];
        if (q < 0) return;
        float lre = Lam[2*p], lim = Lam[2*p+1];
        float step = expf(logstep[p]);
        float a  = expf(lre*step);
        float th = lim*step;
        float lbr = a*cosf(th), lbi = a*sinf(th);
        float den = lre*lre + lim*lim;
        float cr = ((lbr-1.0f)*lre + lbi*lim)/den;
        float ci = (lbi*lre - (lbr-1.0f)*lim)/den;
        float br = Bmat[(p*CDIM + c)*2], bi = Bmat[(p*CDIM + c)*2 + 1];
        g_wb[(size_t)(2*q  )*CDIM + c] = __float2half_rn(cr*br - ci*bi);
        g_wb[(size_t)(2*q+1)*CDIM + c] = __float2half_rn(cr*bi + ci*br);
    } else if (bid < 576){
        if (tid < PDIM){
            int hrow = bid - 192, p = tid;
            int q = g_rank[p];
            if (q < 0) return;
            float cre = Cmat[(hrow*PDIM + p)*2], cim = Cmat[(hrow*PDIM + p)*2 + 1];
            g_wc[(size_t)hrow*CDIM + 2*q]     = __float2half_rn( 2.0f*cre);
            g_wc[(size_t)hrow*CDIM + 2*q + 1] = __float2half_rn(-2.0f*cim);
        }
    } else if (bid < 1344){
        int n = bid - 576, c = tid;
        int src = (n & 1) ? (CDIM + (n >> 1)) : (n >> 1);
        g_we[(size_t)n*CDIM + c] = __float2half_rn(Wenc[(size_t)src*CDIM + c]);
    } else {
        int i = (bid - 1344)*CDIM + tid;
        g_wd[i] = __float2half_rn(Wdec[i]);
    }
}

// ---------------- LayerNorm 1 : x[B,C,L] -> fp16 [BL,C]  (32-wide L tiles, float4) ----------------
__global__ __launch_bounds__(256) void ln1_kernel(const float* __restrict__ x,
                                                  const float* __restrict__ gam,
                                                  const float* __restrict__ bet,
                                                  __half* __restrict__ fxh){
    extern __shared__ float tile[];       // [CDIM][33]
    int b = blockIdx.y, l0 = blockIdx.x*32;
    int tid = threadIdx.x;
    #pragma unroll
    for (int k = 0; k < 12; k++){
        int idx = tid + k*256;
        int c = idx >> 3, seg = idx & 7;
        float4 v = *(const float4*)(x + ((size_t)b*CDIM + c)*LDIM + l0 + seg*4);
        float* tr = tile + c*33 + seg*4;
        tr[0]=v.x; tr[1]=v.y; tr[2]=v.z; tr[3]=v.w;
    }
    __syncthreads();
    int w = tid >> 5, lane = tid & 31;
    #pragma unroll
    for (int jj = 0; jj < 4; jj++){
        int j = w*4 + jj;
        float v[12]; float s = 0.0f;
        #pragma unroll
        for (int k = 0; k < 12; k++){ v[k] = tile[(lane + 32*k)*33 + j]; s += v[k]; }
        #pragma unroll
        for (int o = 16; o; o >>= 1) s += __shfl_xor_sync(0xffffffffu, s, o);
        float mu = s * (1.0f/CDIM);
        float q = 0.0f;
        #pragma unroll
        for (int k = 0; k < 12; k++){ float d = v[k]-mu; q += d*d; }
        #pragma unroll
        for (int o = 16; o; o >>= 1) q += __shfl_xor_sync(0xffffffffu, q, o);
        float inv = rsqrtf(q*(1.0f/CDIM) + 1e-5f);
        size_t row = ((size_t)b*LDIM + l0 + j)*CDIM;
        #pragma unroll
        for (int k = 0; k < 12; k++){
            int c = lane + 32*k;
            float val = (v[k]-mu)*inv*gam[c] + bet[c];
            fxh[row + c] = __float2half_rn(val);
        }
    }
}

// ---------------- LayerNorm 2 : y fp16 [BL,C] -> fp16 ----------------
__global__ __launch_bounds__(256) void ln2_kernel(const __half* __restrict__ y,
                                                  const float* __restrict__ gam,
                                                  const float* __restrict__ bet,
                                                  __half* __restrict__ fyh){
    int row = blockIdx.x*8 + (threadIdx.x >> 5);
    int lane = threadIdx.x & 31;
    const uint2* r2 = (const uint2*)(y + (size_t)row*CDIM);
    float f[12]; float s = 0.0f;
    #pragma unroll
    for (int k = 0; k < 3; k++){
        uint2 u = r2[lane + 32*k];
        float2 fa = __half22float2(*(__half2*)&u.x);
        float2 fb = __half22float2(*(__half2*)&u.y);
        f[k*4+0]=fa.x; f[k*4+1]=fa.y; f[k*4+2]=fb.x; f[k*4+3]=fb.y;
        s += fa.x+fa.y+fb.x+fb.y;
    }
    #pragma unroll
    for (int o = 16; o; o >>= 1) s += __shfl_xor_sync(0xffffffffu, s, o);
    float mu = s * (1.0f/CDIM);
    float q = 0.0f;
    #pragma unroll
    for (int k = 0; k < 12; k++){ float d = f[k]-mu; q += d*d; }
    #pragma unroll
    for (int o = 16; o; o >>= 1) q += __shfl_xor_sync(0xffffffffu, q, o);
    float inv = rsqrtf(q*(1.0f/CDIM) + 1e-5f);
    #pragma unroll
    for (int k = 0; k < 3; k++){
        int c4 = lane + 32*k;
        float4 gg = ((const float4*)gam)[c4], bb = ((const float4*)bet)[c4];
        float rx = (f[k*4+0]-mu)*inv*gg.x + bb.x;
        float ry = (f[k*4+1]-mu)*inv*gg.y + bb.y;
        float rz = (f[k*4+2]-mu)*inv*gg.z + bb.z;
        float rw = (f[k*4+3]-mu)*inv*gg.w + bb.w;
        size_t base = (size_t)row*CDIM + c4*4;
        *(__half2*)(fyh + base)     = __floats2half2_rn(rx, ry);
        *(__half2*)(fyh + base + 2) = __floats2half2_rn(rz, rw);
    }
}

// ---------------- chunked constant-coefficient complex scan (interleaved, compacted) ----------------
__global__ void scan_a(const __half2* __restrict__ bu2, float2* __restrict__ carry2){
    int p = threadIdx.x, ch = blockIdx.x, b = blockIdx.y;
    if (p >= g_cnt) return;
    float lre = g_lam[2*p], lim = g_lam[2*p+1];
    float sre = 0.0f, sim = 0.0f;
    size_t base = ((size_t)b*LDIM + (size_t)ch*TCH)*PDIM;
    #pragma unroll 4
    for (int i = 0; i < TCH; i++){
        float2 v = __half22float2(bu2[base + (size_t)i*PDIM + p]);
        float nr = fmaf(lre, sre, fmaf(-lim, sim, v.x));
        float ni = fmaf(lre, sim, fmaf( lim, sre, v.y));
        sre = nr; sim = ni;
    }
    carry2[((size_t)b*NCH + ch)*PDIM + p] = make_float2(sre, sim);
}

__global__ void scan_b(float2* __restrict__ carry2){
    int p = threadIdx.x, b = blockIdx.x;
    if (p >= g_cnt) return;
    float tr = g_lamT[2*p], ti = g_lamT[2*p+1];
    float pr = 0.0f, pi = 0.0f;
    for (int k = 0; k < NCH; k++){
        size_t ci = ((size_t)b*NCH + k)*PDIM + p;
        float2 cv = carry2[ci];
        carry2[ci] = make_float2(pr, pi);
        float nr = fmaf(tr, pr, fmaf(-ti, pi, cv.x));
        float ni = fmaf(tr, pi, fmaf( ti, pr, cv.y));
        pr = nr; pi = ni;
    }
}

__global__ void scan_c(const __half2* __restrict__ bu2, const float2* __restrict__ carry2,
                       __half2* __restrict__ bh2){
    int p = threadIdx.x, ch = blockIdx.x, b = blockIdx.y;
    if (p >= g_cnt) return;
    float2 seed = carry2[((size_t)b*NCH + ch)*PDIM + p];
    float sre = seed.x, sim = seed.y;
    float lre = g_lam[2*p], lim = g_lam[2*p+1];
    size_t base = ((size_t)b*LDIM + (size_t)ch*TCH)*PDIM;
    #pragma unroll 4
    for (int i = 0; i < TCH; i++){
        size_t idx = base + (size_t)i*PDIM + p;
        float2 v = __half22float2(bu2[idx]);
        float nr = fmaf(lre, sre, fmaf(-lim, sim, v.x));
        float ni = fmaf(lre, sim, fmaf( lim, sre, v.y));
        sre = nr; sim = ni;
        bh2[idx] = __floats2half2_rn(nr, ni);
    }
}

// ---------------- launch ----------------
extern "C" void kernel_launch(void* const* d_in, const int* in_sizes, int n_in,
                              void* d_out, int out_size){
    const float* x       = (const float*)d_in[0];
    const float* ln1g    = (const float*)d_in[1];
    const float* ln1b    = (const float*)d_in[2];
    const float* Lam     = (const float*)d_in[3];
    const float* Bmat    = (const float*)d_in[4];
    const float* Cmat    = (const float*)d_in[5];
    const float* Dv      = (const float*)d_in[6];
    const float* logstep = (const float*)d_in[7];
    const float* ln2g    = (const float*)d_in[8];
    const float* ln2b    = (const float*)d_in[9];
    const float* Wenc    = (const float*)d_in[10];
    const float* Wdec    = (const float*)d_in[11];
    float* out = (float*)d_out;

    float *carry;
    cudaGetSymbolAddress((void**)&carry, g_carry);

    __half *buf,*fxh,*buh,*yh,*fyh,*ggh,*wb,*wc,*we,*wd;
    cudaGetSymbolAddress((void**)&buf, g_buf);
    cudaGetSymbolAddress((void**)&fxh, g_fxh);
    cudaGetSymbolAddress((void**)&buh, g_buh);
    cudaGetSymbolAddress((void**)&yh,  g_yh);
    cudaGetSymbolAddress((void**)&fyh, g_fyh);
    cudaGetSymbolAddress((void**)&ggh, g_ggh);
    cudaGetSymbolAddress((void**)&wb,  g_wb);  cudaGetSymbolAddress((void**)&wc,  g_wc);
    cudaGetSymbolAddress((void**)&we,  g_we);  cudaGetSymbolAddress((void**)&wd,  g_wd);

    const int SMEM_GEMM = 3*36864;   // 110592 B (3-stage BK=64; covers EPI staging)
    cudaFuncSetAttribute(mma_gemm<1>, cudaFuncAttributeMaxDynamicSharedMemorySize, SMEM_GEMM);
    cudaFuncSetAttribute(mma_gemm<3>, cudaFuncAttributeMaxDynamicSharedMemorySize, SMEM_GEMM);
    cudaFuncSetAttribute(mma_gemm<4>, cudaFuncAttributeMaxDynamicSharedMemorySize, SMEM_GEMM);
    cudaFuncSetAttribute(mma_gemm<5>, cudaFuncAttributeMaxDynamicSharedMemorySize, SMEM_GEMM);
    const int SMEM_LN1 = CDIM*33*4;  // 50688 B
    cudaFuncSetAttribute(ln1_kernel, cudaFuncAttributeMaxDynamicSharedMemorySize, SMEM_LN1);

    // launch 1-2: prep (mask compaction + weights)
    prep_lam<<<1, PDIM>>>(Lam, logstep);
    prep_all<<<1728, CDIM>>>(Lam, logstep, Bmat, Cmat, Wenc, Wdec);

    // launch 3
    ln1_kernel<<<dim3(LDIM/32, BSZ), 256, SMEM_LN1>>>(x, ln1g, ln1b, fxh);

    // launch 4 (ncu capture slot): Bu = fx @ Bbar^T -> fp16 interleaved, only active tiles
    mma_gemm<5><<<dim3(3, 512), 512, SMEM_GEMM>>>(fxh, wb, nullptr, CDIM,
                                                  buf, nullptr, nullptr);

    // launch 5-7: scan (interleaved complex, compacted to g_cnt pairs)
    scan_a<<<dim3(NCH, BSZ), PDIM>>>((const __half2*)buf, (float2*)carry);
    scan_b<<<BSZ, PDIM>>>((float2*)carry);
    scan_c<<<dim3(NCH, BSZ), PDIM>>>((const __half2*)buf, (const float2*)carry, (__half2*)buh);

    // launch 8: y = gelu(xs @ Ceff^T + D*fx) + fx  -> fp16  (dynamic K = g_nch2 chunks)
    mma_gemm<1><<<dim3(3, 512), 512, SMEM_GEMM>>>(buh, wc, nullptr, CDIM,
                                                  yh, fxh, Dv);

    // launch 9
    ln2_kernel<<<BLTOK/8, 256>>>(yh, ln2g, ln2b, fyh);

    // launch 10: gg = GEGLU(fy @ Wenc_interleaved^T) -> fp16 [BL, 384]
    mma_gemm<3><<<dim3(6, 512), 512, SMEM_GEMM>>>(fyh, we, nullptr, CDIM,
                                                  ggh, nullptr, nullptr);

    // launch 11: out = transpose(gg @ Wdec^T + fy) -> [B,C,L] fp32
    mma_gemm<4><<<dim3(3, 512), 512, SMEM_GEMM>>>(ggh, wd, out, CDIM,
                                                  nullptr, fyh, nullptr);
}